// round 15
// baseline (speedup 1.0000x reference)
#include <cuda_runtime.h>
#include <cstdint>

// ---------------------------------------------------------------------------
// SLAYER SNN pipeline, t-major intermediates:
//   K0 : pool4 input (n,c,256,256,t) -> p0 (n,t,2,64,64)   [DRAM 71%]
//   K1a: conv1 (2->4) h-split grid 800 (no reg cap), 8px x 4oc
//   K1b: spike scan over t + fused 4x4 pool -> p1
//   K2a: conv2 (4->8) 4-way ci-split, grid 1600 -> u2 partials
//   K2b: sum 4 partials ((c0+c1)+(c2+c3)) + spike scan -> s2 bytes
//   K3 : dp4a pool + einsum wl -> out (n,2,t)
// Capture slot: 2 dummies -> ncu capture (4th launch) = k1a.
// ---------------------------------------------------------------------------

#define NB 4
#define TT 100

__device__ float g_p0[NB*TT*2*64*64];          // 3,276,800 floats
__device__ float g_u1[NB*TT*4*64*64];          // 6,553,600 floats
__device__ float g_p1[NB*TT*4*16*16];          //   409,600 floats
__device__ float g_u2p[4*NB*TT*8*16*16];       // 3,276,800 floats (ci partials)
__device__ unsigned char g_s2[NB*TT*8*16*16];  //   819,200 bytes

// ---- packed f32x2 helpers (sm_100+) ----
__device__ __forceinline__ unsigned long long pack2(float lo, float hi) {
    unsigned long long r;
    asm("mov.b64 %0, {%1, %2};" : "=l"(r) : "f"(lo), "f"(hi));
    return r;
}
__device__ __forceinline__ void unpack2(unsigned long long v, float& lo, float& hi) {
    asm("mov.b64 {%0, %1}, %2;" : "=f"(lo), "=f"(hi) : "l"(v));
}
__device__ __forceinline__ unsigned long long fma2(unsigned long long a,
                                                   unsigned long long b,
                                                   unsigned long long c) {
    unsigned long long d;
    asm("fma.rn.f32x2 %0, %1, %2, %3;" : "=l"(d) : "l"(a), "l"(b), "l"(c));
    return d;
}
__device__ __forceinline__ int dp4a_sum(unsigned int u, int acc) {
    int r;
    asm("dp4a.u32.u32 %0, %1, %2, %3;" : "=r"(r)
        : "r"(u), "r"(0x01010101u), "r"(acc));
    return r;
}
// FSET.GE: 1.0f / 0.0f as data (4-cyc, avoids 13-cyc predicate path)
__device__ __forceinline__ float fset_ge1(float a) {
    float d;
    asm("set.ge.f32.f32 %0, %1, 0f3F800000;" : "=f"(d) : "f"(a));
    return d;
}

// ---------------------------------------------------------------------------
// Dummy: empty kernel used to shift the fixed ncu capture slot.
// ---------------------------------------------------------------------------
__global__ void k_dummy() {}

// ---------------------------------------------------------------------------
// K0: 4x4 average pool of raw input with layout transpose to t-major.
// 512 blocks = (n,c,H64), 512 threads (DRAM-bound, 70.8% of HBM spec).
// ---------------------------------------------------------------------------
__global__ void __launch_bounds__(512) k0_pool(const float* __restrict__ in) {
    const int b = blockIdx.x;
    const int n = b >> 7, c = (b >> 6) & 1, H = b & 63;
    __shared__ float sm[TT][65];   // [t][W]

    const float* base = in + (size_t)((n*2 + c)*256 + H*4) * 25600;

    for (int idx = threadIdx.x; idx < 1600; idx += 512) {
        int W  = idx / 25;
        int tq = idx - W*25;           // t-quad 0..24
        const float4* p = (const float4*)(base + (size_t)(W*4)*100 + tq*4);
        float4 s = make_float4(0.f, 0.f, 0.f, 0.f);
#pragma unroll
        for (int dy = 0; dy < 4; dy++)
#pragma unroll
            for (int dx = 0; dx < 4; dx++) {
                float4 v = p[dy*6400 + dx*25];
                s.x += v.x; s.y += v.y; s.z += v.z; s.w += v.w;
            }
        int t = tq*4;
        sm[t+0][W] = s.x*0.0625f; sm[t+1][W] = s.y*0.0625f;
        sm[t+2][W] = s.z*0.0625f; sm[t+3][W] = s.w*0.0625f;
    }
    __syncthreads();
    const size_t ob = ((size_t)(n*TT)*2 + c)*4096 + H*64;
    for (int idx = threadIdx.x; idx < 6400; idx += 512) {
        int t = idx >> 6, W = idx & 63;
        g_p0[ob + (size_t)t*8192 + W] = sm[t][W];
    }
}

// ---------------------------------------------------------------------------
// K1a: conv1 2->4ch 7x7 pad3 on 64x64, SPLIT over h-halves: grid 800 =
// (slab, hhalf), 256 threads, NO reg cap (the R11 launch_bounds(256,4)
// spill is what regressed). Block computes 32 output rows from a 38-row
// halo tile; no partial sums; per-output (ci,dy,dx) order unchanged ->
// bit-identical results. smem 23.5KB, ~68 regs -> 3 blocks/SM (24 warps).
// ---------------------------------------------------------------------------
__global__ void __launch_bounds__(256) k1a_conv1(const float* __restrict__ w0g) {
    const int bb = blockIdx.x;             // 0..799
    const int b = bb >> 1, half = bb & 1;  // slab, h-half
    __shared__ __align__(16) float si[2*38*72];   // halo tile, stride 72
    __shared__ unsigned long long wp0[196];       // [op2][ci2][dy7][dx7] pairs

    for (int i = threadIdx.x; i < 196; i += 256) {
        int op = i / 98, q = i - op*98;
        wp0[i] = pack2(w0g[(2*op)*98 + q], w0g[(2*op+1)*98 + q]);
    }
    // vectorized zero-fill: 5472 floats = 1368 float4
    for (int i = threadIdx.x; i < 1368; i += 256)
        ((float4*)si)[i] = make_float4(0.f, 0.f, 0.f, 0.f);
    __syncthreads();
    const float* slab = g_p0 + (size_t)b * 8192;
    // halo fill: local padded row lr <- input row r = lr + half*32 - 3
    // 2 ci x 38 rows x 16 float4 = 1216 vector loads
    for (int i = threadIdx.x; i < 1216; i += 256) {
        int ci = i / 608, rem = i - ci*608;
        int lr = rem >> 4, wq = rem & 15;
        int r = lr + half*32 - 3;
        if (r >= 0 && r < 64) {
            float4 v = ((const float4*)(slab + ci*4096 + r*64))[wq];
            float* d = si + ci*2736 + lr*72 + (wq << 2) + 3;
            d[0] = v.x; d[1] = v.y; d[2] = v.z; d[3] = v.w;
        }
    }
    __syncthreads();

    float* out = g_u1 + (size_t)b * 16384;

    const int pos = threadIdx.x;                // 0..255
    const int hl  = pos >> 3;                   // local row 0..31
    const int ws  = (pos & 7) << 3;             // 8-pixel segment start
    const int ha  = half*32 + hl;               // absolute output row
    unsigned long long acc[2][8];
#pragma unroll
    for (int op = 0; op < 2; op++)
#pragma unroll
        for (int px = 0; px < 8; px++) acc[op][px] = 0ull;

#pragma unroll 1
    for (int ci = 0; ci < 2; ci++) {
#pragma unroll 1
        for (int dy = 0; dy < 7; dy++) {
            const float* r = si + ci*2736 + (hl+dy)*72 + ws;  // 16B-aligned
            float v[16];
#pragma unroll
            for (int q = 0; q < 4; q++) {
                float4 t4 = ((const float4*)r)[q];
                v[4*q+0] = t4.x; v[4*q+1] = t4.y;
                v[4*q+2] = t4.z; v[4*q+3] = t4.w;
            }
            unsigned long long pd[14];
#pragma unroll
            for (int j = 0; j < 14; j++) pd[j] = pack2(v[j], v[j]);
            const unsigned long long* wr = wp0 + ci*49 + dy*7;  // +op*98+dx
#pragma unroll
            for (int dx = 0; dx < 7; dx++) {
                unsigned long long wa = wr[dx];        // oc pair (0,1)
                unsigned long long wb = wr[98 + dx];   // oc pair (2,3)
#pragma unroll
                for (int px = 0; px < 8; px++) {
                    acc[0][px] = fma2(pd[px+dx], wa, acc[0][px]);
                    acc[1][px] = fma2(pd[px+dx], wb, acc[1][px]);
                }
            }
        }
    }
#pragma unroll
    for (int op = 0; op < 2; op++) {
        float lo[8], hi[8];
#pragma unroll
        for (int px = 0; px < 8; px++) unpack2(acc[op][px], lo[px], hi[px]);
        float4* d0 = (float4*)(out + (2*op  )*4096 + ha*64 + ws);
        float4* d1 = (float4*)(out + (2*op+1)*4096 + ha*64 + ws);
        d0[0] = make_float4(lo[0], lo[1], lo[2], lo[3]);
        d0[1] = make_float4(lo[4], lo[5], lo[6], lo[7]);
        d1[0] = make_float4(hi[0], hi[1], hi[2], hi[3]);
        d1[1] = make_float4(hi[4], hi[5], hi[6], hi[7]);
    }
}

// ---------------------------------------------------------------------------
// K1b: spike scan layer 1 + fused 4x4 pool -> p1. Depth-8 double-banked
// prefetch, FSET spike math. Thread = (n,c,ph,pw,hi); pool via 2 shfl_xor.
// ---------------------------------------------------------------------------
__global__ void __launch_bounds__(64) k1b_scan1() {
    const int g = blockIdx.x*64 + threadIdx.x;      // 0..16383
    const int hi = g & 3, pw = (g >> 2) & 15, ph = (g >> 6) & 15;
    const int c = (g >> 10) & 3, n = g >> 12;

    const float4* ub = (const float4*)g_u1
        + ((size_t)(n*TT)*4 + c)*1024 + (ph*4 + hi)*16 + pw;   // +t*4096
    float* pb = g_p1 + ((size_t)(n*TT)*4 + c)*256 + ph*16 + pw; // +t*1024

    float m0 = 0.f, m1 = 0.f, m2 = 0.f, m3 = 0.f;
    float4 A[4], B[4];
#pragma unroll
    for (int i = 0; i < 4; i++) { A[i] = ub[(size_t)i*4096];
                                  B[i] = ub[(size_t)(4+i)*4096]; }

#define K1B_GROUP(BANK, T0)                                                  \
    {                                                                        \
        float ps[4];                                                         \
        _Pragma("unroll")                                                    \
        for (int i = 0; i < 4; i++) {                                        \
            float4 u = BANK[i];                                              \
            m0 += u.x; float s0 = fset_ge1(m0); m0 -= s0;                    \
            m1 += u.y; float s1 = fset_ge1(m1); m1 -= s1;                    \
            m2 += u.z; float s2 = fset_ge1(m2); m2 -= s2;                    \
            m3 += u.w; float s3 = fset_ge1(m3); m3 -= s3;                    \
            ps[i] = (s0 + s1) + (s2 + s3);                                   \
        }                                                                    \
        _Pragma("unroll")                                                    \
        for (int i = 0; i < 4; i++)                                          \
            ps[i] += __shfl_xor_sync(0xffffffffu, ps[i], 1);                 \
        _Pragma("unroll")                                                    \
        for (int i = 0; i < 4; i++)                                          \
            ps[i] += __shfl_xor_sync(0xffffffffu, ps[i], 2);                 \
        if (hi == 0) {                                                       \
            _Pragma("unroll")                                                \
            for (int i = 0; i < 4; i++)                                      \
                pb[(size_t)((T0) + i)*1024] = ps[i] * 0.0625f;               \
        }                                                                    \
    }

#pragma unroll 1
    for (int tp = 0; tp < 12; tp++) {
        K1B_GROUP(A, tp*8);
#pragma unroll
        for (int i = 0; i < 4; i++) A[i] = ub[(size_t)(tp*8 + 8 + i)*4096];
        K1B_GROUP(B, tp*8 + 4);
        if (tp < 11) {
#pragma unroll
            for (int i = 0; i < 4; i++)
                B[i] = ub[(size_t)(tp*8 + 12 + i)*4096];
        }
    }
    K1B_GROUP(A, 96);
#undef K1B_GROUP
}

// ---------------------------------------------------------------------------
// K2a: conv2 4->8ch 7x7 pad3 on 16x16, 4-WAY ci-split, grid 1600.
// Block = (slab, ci); 128 threads = 4 oc-pair groups x 32 px-threads;
// thread = 8 px x 1 oc-pair over ONE input channel.
// ---------------------------------------------------------------------------
__global__ void __launch_bounds__(128) k2a_conv2(const float* __restrict__ w1g) {
    const int b = blockIdx.x;                   // 0..1599
    const int slab = b >> 2, ci = b & 3;
    __shared__ __align__(16) float pp[22*24];   // one padded ci plane (528)
    __shared__ unsigned long long wq[196];      // [op4][dy7][dx7] oc pairs

    const int tid = threadIdx.x;
    for (int i = tid; i < 196; i += 128) {
        int op = i / 49, r = i - op*49;
        wq[i] = pack2(w1g[(2*op  )*196 + ci*49 + r],
                      w1g[(2*op+1)*196 + ci*49 + r]);
    }
    for (int i = tid; i < 528; i += 128) pp[i] = 0.f;
    __syncthreads();
    const float* slabp = g_p1 + (size_t)slab * 1024 + ci*256;
    for (int i = tid; i < 256; i += 128) {
        int ph = i >> 4, pw = i & 15;
        pp[(ph+3)*24 + (pw+3)] = slabp[i];
    }
    __syncthreads();

    const int ocp = tid >> 5;                // 0..3: oc pair (2ocp, 2ocp+1)
    const int l = tid & 31;
    const int h = l >> 1, ws = (l & 1) << 3; // 8-pixel segment
    unsigned long long acc[8];
#pragma unroll
    for (int px = 0; px < 8; px++) acc[px] = 0ull;

#pragma unroll
    for (int dy = 0; dy < 7; dy++) {
        const float* row = pp + (h+dy)*24 + ws;        // 16B-aligned
        float v[16];
#pragma unroll
        for (int q = 0; q < 4; q++) {
            float4 t4 = ((const float4*)row)[q];
            v[4*q+0] = t4.x; v[4*q+1] = t4.y;
            v[4*q+2] = t4.z; v[4*q+3] = t4.w;
        }
        unsigned long long pd[14];
#pragma unroll
        for (int j = 0; j < 14; j++) pd[j] = pack2(v[j], v[j]);
        const unsigned long long* wr = wq + ocp*49 + dy*7;
        unsigned long long wv[7];
#pragma unroll
        for (int dx = 0; dx < 7; dx++) wv[dx] = wr[dx];
#pragma unroll
        for (int dx = 0; dx < 7; dx++) {
#pragma unroll
            for (int px = 0; px < 8; px++)
                acc[px] = fma2(pd[px+dx], wv[dx], acc[px]);
        }
    }
    float* out = g_u2p + (size_t)ci*(NB*TT*2048)
               + (size_t)slab*2048 + (2*ocp)*256 + h*16 + ws;
    float lo[8], hi[8];
#pragma unroll
    for (int px = 0; px < 8; px++) unpack2(acc[px], lo[px], hi[px]);
    float4* d0 = (float4*)out;             // oc 2*ocp
    float4* d1 = (float4*)(out + 256);     // oc 2*ocp+1
    d0[0] = make_float4(lo[0], lo[1], lo[2], lo[3]);
    d0[1] = make_float4(lo[4], lo[5], lo[6], lo[7]);
    d1[0] = make_float4(hi[0], hi[1], hi[2], hi[3]);
    d1[1] = make_float4(hi[4], hi[5], hi[6], hi[7]);
}

// ---------------------------------------------------------------------------
// K2b: sum 4 ci partials as (c0+c1)+(c2+c3) + spike scan -> s2 bytes.
// Double-banked prefetch of 4t x 4 streams.
// ---------------------------------------------------------------------------
__global__ void __launch_bounds__(32) k2b_scan2() {
    const int g = blockIdx.x*32 + threadIdx.x;      // 0..8191
    const int n = g >> 11, r = g & 2047;
    const size_t base = (size_t)(n*TT)*2048 + r;
    const size_t PL = (size_t)(NB*TT*2048);
    const float* p0 = g_u2p + base;
    const float* p1 = g_u2p + PL   + base;
    const float* p2 = g_u2p + 2*PL + base;
    const float* p3 = g_u2p + 3*PL + base;
    unsigned char* sp = g_s2 + base;

    float A0[4], A1[4], A2[4], A3[4];
    float B0[4], B1[4], B2[4], B3[4];
#pragma unroll
    for (int i = 0; i < 4; i++) {
        A0[i] = p0[(size_t)i*2048];     A1[i] = p1[(size_t)i*2048];
        A2[i] = p2[(size_t)i*2048];     A3[i] = p3[(size_t)i*2048];
        B0[i] = p0[(size_t)(4+i)*2048]; B1[i] = p1[(size_t)(4+i)*2048];
        B2[i] = p2[(size_t)(4+i)*2048]; B3[i] = p3[(size_t)(4+i)*2048];
    }
    float m = 0.f;

#define K2B_GROUP(Q0, Q1, Q2, Q3, T0)                                        \
    {                                                                        \
        _Pragma("unroll")                                                    \
        for (int i = 0; i < 4; i++) {                                        \
            float u = (Q0[i] + Q1[i]) + (Q2[i] + Q3[i]);                     \
            m += u;                                                          \
            float s = fset_ge1(m);                                           \
            m -= s;                                                          \
            sp[(size_t)((T0) + i)*2048] = (unsigned char)s;                  \
        }                                                                    \
    }

#pragma unroll 1
    for (int tp = 0; tp < 12; tp++) {
        K2B_GROUP(A0, A1, A2, A3, tp*8);
#pragma unroll
        for (int i = 0; i < 4; i++) {
            A0[i] = p0[(size_t)(tp*8 + 8 + i)*2048];
            A1[i] = p1[(size_t)(tp*8 + 8 + i)*2048];
            A2[i] = p2[(size_t)(tp*8 + 8 + i)*2048];
            A3[i] = p3[(size_t)(tp*8 + 8 + i)*2048];
        }
        K2B_GROUP(B0, B1, B2, B3, tp*8 + 4);
        if (tp < 11) {
#pragma unroll
            for (int i = 0; i < 4; i++) {
                B0[i] = p0[(size_t)(tp*8 + 12 + i)*2048];
                B1[i] = p1[(size_t)(tp*8 + 12 + i)*2048];
                B2[i] = p2[(size_t)(tp*8 + 12 + i)*2048];
                B3[i] = p3[(size_t)(tp*8 + 12 + i)*2048];
            }
        }
    }
    K2B_GROUP(A0, A1, A2, A3, 96);
#undef K2B_GROUP
}

// ---------------------------------------------------------------------------
// K3: dp4a pool of s2 + einsum with wl -> out (n,2,t). 400 blocks x 64 thr.
// ---------------------------------------------------------------------------
__global__ void __launch_bounds__(64) k3_out(const float* __restrict__ wlg,
                                             float* __restrict__ out) {
    const int b = blockIdx.x;
    const int n = b / 100, t = b - n*100;
    const unsigned int* slab = (const unsigned int*)(g_s2 + (size_t)b * 2048);
    const int tid = threadIdx.x;
    float a0 = 0.f, a1 = 0.f;
    for (int i = tid; i < 512; i += 64) {
        int cnt = dp4a_sum(slab[i], 0);
        int cc = i >> 6;
        int hh = (i >> 2) & 15;
        int wq = i & 3;
        int wi = cc*16 + (hh >> 2)*4 + wq;
        float f = (float)cnt;
        a0 += f * wlg[wi];
        a1 += f * wlg[128 + wi];
    }
    __shared__ float r0[64], r1[64];
    r0[tid] = a0; r1[tid] = a1;
    __syncthreads();
    if (tid < 32) {
        float v0 = r0[tid] + r0[tid+32];
        float v1 = r1[tid] + r1[tid+32];
#pragma unroll
        for (int off = 16; off > 0; off >>= 1) {
            v0 += __shfl_down_sync(0xffffffffu, v0, off);
            v1 += __shfl_down_sync(0xffffffffu, v1, off);
        }
        if (tid == 0) {
            out[(n*2 + 0)*100 + t] = v0 * 0.0625f;
            out[(n*2 + 1)*100 + t] = v1 * 0.0625f;
        }
    }
}

// ---------------------------------------------------------------------------
extern "C" void kernel_launch(void* const* d_in, const int* in_sizes, int n_in,
                              void* d_out, int out_size) {
    (void)in_sizes; (void)n_in; (void)out_size;
    const float* data = (const float*)d_in[0];
    const float* w0g  = (const float*)d_in[1];
    const float* w1g  = (const float*)d_in[2];
    const float* wlg  = (const float*)d_in[3];

    // Capture-slot shift: two dummies keep the ncu capture (4th launch)
    // on k1a_conv1 to verify this round's change directly.
    k_dummy  <<<   1,  32>>>();
    k_dummy  <<<   1,  32>>>();

    k0_pool  <<< 512, 512>>>(data);
    k1a_conv1<<< 800, 256>>>(w0g);
    k1b_scan1<<< 256,  64>>>();
    k2a_conv2<<<1600, 128>>>(w1g);
    k2b_scan2<<< 256,  32>>>();
    k3_out   <<< 400,  64>>>(wlg, (float*)d_out);
}

// round 16
// speedup vs baseline: 1.0354x; 1.0354x over previous
#include <cuda_runtime.h>
#include <cstdint>

// ---------------------------------------------------------------------------
// SLAYER SNN pipeline, t-major intermediates:
//   K0 : pool4 input (n,c,256,256,t) -> p0 (n,t,2,64,64)   [DRAM 71%]
//   K1a: conv1 (2->4) per slab, 256 thr, 8px x 4oc          [R14 best]
//   K1b: spike scan + fused pool, RING-4 prefetch (16 loads in flight)
//   K2a: conv2 (4->8) 4-way ci-split, grid 1600 -> u2 partials
//   K2b: sum 4 partials + spike scan -> s2 bytes
//   K3 : dp4a pool + einsum wl -> out (n,2,t)
// Capture slot: 1 dummy -> ncu capture (4th launch) = k1b.
// ---------------------------------------------------------------------------

#define NB 4
#define TT 100

__device__ float g_p0[NB*TT*2*64*64];          // 3,276,800 floats
__device__ float g_u1[NB*TT*4*64*64];          // 6,553,600 floats
__device__ float g_p1[NB*TT*4*16*16];          //   409,600 floats
__device__ float g_u2p[4*NB*TT*8*16*16];       // 3,276,800 floats (ci partials)
__device__ unsigned char g_s2[NB*TT*8*16*16];  //   819,200 bytes

// ---- packed f32x2 helpers (sm_100+) ----
__device__ __forceinline__ unsigned long long pack2(float lo, float hi) {
    unsigned long long r;
    asm("mov.b64 %0, {%1, %2};" : "=l"(r) : "f"(lo), "f"(hi));
    return r;
}
__device__ __forceinline__ void unpack2(unsigned long long v, float& lo, float& hi) {
    asm("mov.b64 {%0, %1}, %2;" : "=f"(lo), "=f"(hi) : "l"(v));
}
__device__ __forceinline__ unsigned long long fma2(unsigned long long a,
                                                   unsigned long long b,
                                                   unsigned long long c) {
    unsigned long long d;
    asm("fma.rn.f32x2 %0, %1, %2, %3;" : "=l"(d) : "l"(a), "l"(b), "l"(c));
    return d;
}
__device__ __forceinline__ int dp4a_sum(unsigned int u, int acc) {
    int r;
    asm("dp4a.u32.u32 %0, %1, %2, %3;" : "=r"(r)
        : "r"(u), "r"(0x01010101u), "r"(acc));
    return r;
}
// FSET.GE: 1.0f / 0.0f as data (4-cyc, avoids 13-cyc predicate path)
__device__ __forceinline__ float fset_ge1(float a) {
    float d;
    asm("set.ge.f32.f32 %0, %1, 0f3F800000;" : "=f"(d) : "f"(a));
    return d;
}

// ---------------------------------------------------------------------------
// Dummy: empty kernel used to shift the fixed ncu capture slot.
// ---------------------------------------------------------------------------
__global__ void k_dummy() {}

// ---------------------------------------------------------------------------
// K0: 4x4 average pool of raw input with layout transpose to t-major.
// 512 blocks = (n,c,H64), 512 threads (DRAM-bound, 70.8% of HBM spec).
// ---------------------------------------------------------------------------
__global__ void __launch_bounds__(512) k0_pool(const float* __restrict__ in) {
    const int b = blockIdx.x;
    const int n = b >> 7, c = (b >> 6) & 1, H = b & 63;
    __shared__ float sm[TT][65];   // [t][W]

    const float* base = in + (size_t)((n*2 + c)*256 + H*4) * 25600;

    for (int idx = threadIdx.x; idx < 1600; idx += 512) {
        int W  = idx / 25;
        int tq = idx - W*25;           // t-quad 0..24
        const float4* p = (const float4*)(base + (size_t)(W*4)*100 + tq*4);
        float4 s = make_float4(0.f, 0.f, 0.f, 0.f);
#pragma unroll
        for (int dy = 0; dy < 4; dy++)
#pragma unroll
            for (int dx = 0; dx < 4; dx++) {
                float4 v = p[dy*6400 + dx*25];
                s.x += v.x; s.y += v.y; s.z += v.z; s.w += v.w;
            }
        int t = tq*4;
        sm[t+0][W] = s.x*0.0625f; sm[t+1][W] = s.y*0.0625f;
        sm[t+2][W] = s.z*0.0625f; sm[t+3][W] = s.w*0.0625f;
    }
    __syncthreads();
    const size_t ob = ((size_t)(n*TT)*2 + c)*4096 + H*64;
    for (int idx = threadIdx.x; idx < 6400; idx += 512) {
        int t = idx >> 6, W = idx & 63;
        g_p0[ob + (size_t)t*8192 + W] = sm[t][W];
    }
}

// ---------------------------------------------------------------------------
// K1a: conv1 2->4ch 7x7 pad3 on 64x64, one (n,t) slab per block, 256 threads.
// Thread = 8 px x 4 oc (two oc-pair acc banks). R14 version (best total).
// ---------------------------------------------------------------------------
__global__ void __launch_bounds__(256, 2) k1a_conv1(const float* __restrict__ w0g) {
    const int b = blockIdx.x;              // n*100 + t
    __shared__ __align__(16) float si[2*70*72];   // zero-padded, stride 72
    __shared__ unsigned long long wp0[196];  // [op2][ci2][dy7][dx7] oc pairs

    for (int i = threadIdx.x; i < 196; i += 256) {
        int op = i / 98, q = i - op*98;
        wp0[i] = pack2(w0g[(2*op)*98 + q], w0g[(2*op+1)*98 + q]);
    }
    for (int i = threadIdx.x; i < 2520; i += 256)
        ((float4*)si)[i] = make_float4(0.f, 0.f, 0.f, 0.f);
    __syncthreads();
    const float4* slab4 = (const float4*)(g_p0 + (size_t)b * 8192);
    for (int i = threadIdx.x; i < 2048; i += 256) {
        float4 v = slab4[i];               // coalesced LDG.128
        int idx = i << 2;
        int ci = idx >> 12, h = (idx >> 6) & 63, w = idx & 63;
        float* d = si + ci*5040 + (h+3)*72 + (w+3);
        d[0] = v.x; d[1] = v.y; d[2] = v.z; d[3] = v.w;
    }
    __syncthreads();

    float* out = g_u1 + (size_t)b * 16384;

#pragma unroll 1
    for (int rep = 0; rep < 2; rep++) {
        const int pos = threadIdx.x + (rep << 8);   // 0..511
        const int h  = pos >> 3;
        const int ws = (pos & 7) << 3;              // 8-pixel segment start
        unsigned long long acc[2][8];
#pragma unroll
        for (int op = 0; op < 2; op++)
#pragma unroll
            for (int px = 0; px < 8; px++) acc[op][px] = 0ull;

#pragma unroll 1
        for (int ci = 0; ci < 2; ci++) {
#pragma unroll 1
            for (int dy = 0; dy < 7; dy++) {
                const float* r = si + ci*5040 + (h+dy)*72 + ws;  // 16B-aligned
                float v[16];
#pragma unroll
                for (int q = 0; q < 4; q++) {
                    float4 t4 = ((const float4*)r)[q];
                    v[4*q+0] = t4.x; v[4*q+1] = t4.y;
                    v[4*q+2] = t4.z; v[4*q+3] = t4.w;
                }
                unsigned long long pd[14];
#pragma unroll
                for (int j = 0; j < 14; j++) pd[j] = pack2(v[j], v[j]);
                const unsigned long long* wr = wp0 + ci*49 + dy*7;  // +op*98+dx
#pragma unroll
                for (int dx = 0; dx < 7; dx++) {
                    unsigned long long wa = wr[dx];        // oc pair (0,1)
                    unsigned long long wb = wr[98 + dx];   // oc pair (2,3)
#pragma unroll
                    for (int px = 0; px < 8; px++) {
                        acc[0][px] = fma2(pd[px+dx], wa, acc[0][px]);
                        acc[1][px] = fma2(pd[px+dx], wb, acc[1][px]);
                    }
                }
            }
        }
#pragma unroll
        for (int op = 0; op < 2; op++) {
            float lo[8], hi[8];
#pragma unroll
            for (int px = 0; px < 8; px++) unpack2(acc[op][px], lo[px], hi[px]);
            float4* d0 = (float4*)(out + (2*op  )*4096 + h*64 + ws);
            float4* d1 = (float4*)(out + (2*op+1)*4096 + h*64 + ws);
            d0[0] = make_float4(lo[0], lo[1], lo[2], lo[3]);
            d0[1] = make_float4(lo[4], lo[5], lo[6], lo[7]);
            d1[0] = make_float4(hi[0], hi[1], hi[2], hi[3]);
            d1[1] = make_float4(hi[4], hi[5], hi[6], hi[7]);
        }
    }
}

// ---------------------------------------------------------------------------
// K1b: spike scan layer 1 + fused 4x4 pool -> p1. RING-4 prefetch: 4 banks
// of 4 timesteps, each refilled 16 t ahead right after processing -> up to
// 16 float4 loads in flight (vs 8 before). Only 3.5 warps/SM, so registers
// are free. FSET spike math, shfl pool. Bit-identical accumulation order.
// ---------------------------------------------------------------------------
__global__ void __launch_bounds__(64) k1b_scan1() {
    const int g = blockIdx.x*64 + threadIdx.x;      // 0..16383
    const int hi = g & 3, pw = (g >> 2) & 15, ph = (g >> 6) & 15;
    const int c = (g >> 10) & 3, n = g >> 12;

    const float4* ub = (const float4*)g_u1
        + ((size_t)(n*TT)*4 + c)*1024 + (ph*4 + hi)*16 + pw;   // +t*4096
    float* pb = g_p1 + ((size_t)(n*TT)*4 + c)*256 + ph*16 + pw; // +t*1024

    float m0 = 0.f, m1 = 0.f, m2 = 0.f, m3 = 0.f;
    float4 A[4], B[4], C[4], D[4];
#pragma unroll
    for (int i = 0; i < 4; i++) {
        A[i] = ub[(size_t)(i     )*4096];
        B[i] = ub[(size_t)(i +  4)*4096];
        C[i] = ub[(size_t)(i +  8)*4096];
        D[i] = ub[(size_t)(i + 12)*4096];
    }

#define K1B_GROUP(BANK, T0)                                                  \
    {                                                                        \
        float ps[4];                                                         \
        _Pragma("unroll")                                                    \
        for (int i = 0; i < 4; i++) {                                        \
            float4 u = BANK[i];                                              \
            m0 += u.x; float s0 = fset_ge1(m0); m0 -= s0;                    \
            m1 += u.y; float s1 = fset_ge1(m1); m1 -= s1;                    \
            m2 += u.z; float s2 = fset_ge1(m2); m2 -= s2;                    \
            m3 += u.w; float s3 = fset_ge1(m3); m3 -= s3;                    \
            ps[i] = (s0 + s1) + (s2 + s3);                                   \
        }                                                                    \
        _Pragma("unroll")                                                    \
        for (int i = 0; i < 4; i++)                                          \
            ps[i] += __shfl_xor_sync(0xffffffffu, ps[i], 1);                 \
        _Pragma("unroll")                                                    \
        for (int i = 0; i < 4; i++)                                          \
            ps[i] += __shfl_xor_sync(0xffffffffu, ps[i], 2);                 \
        if (hi == 0) {                                                       \
            _Pragma("unroll")                                                \
            for (int i = 0; i < 4; i++)                                      \
                pb[(size_t)((T0) + i)*1024] = ps[i] * 0.0625f;               \
        }                                                                    \
    }
#define K1B_RELOAD(BANK, T0)                                                 \
    {                                                                        \
        _Pragma("unroll")                                                    \
        for (int i = 0; i < 4; i++)                                          \
            BANK[i] = ub[(size_t)((T0) + i)*4096];                           \
    }

#pragma unroll 1
    for (int tp = 0; tp < 6; tp++) {
        const int t0 = tp*16;
        K1B_GROUP(A, t0);
        if (t0 + 16 < TT) K1B_RELOAD(A, t0 + 16);
        K1B_GROUP(B, t0 + 4);
        if (t0 + 20 < TT) K1B_RELOAD(B, t0 + 20);
        K1B_GROUP(C, t0 + 8);
        if (t0 + 24 < TT) K1B_RELOAD(C, t0 + 24);
        K1B_GROUP(D, t0 + 12);
        if (t0 + 28 < TT) K1B_RELOAD(D, t0 + 28);
    }
    K1B_GROUP(A, 96);    // groups 0..23 in loop (t=0..95) + tail t=96..99
#undef K1B_GROUP
#undef K1B_RELOAD
}

// ---------------------------------------------------------------------------
// K2a: conv2 4->8ch 7x7 pad3 on 16x16, 4-WAY ci-split, grid 1600.
// Block = (slab, ci); 128 threads = 4 oc-pair groups x 32 px-threads;
// thread = 8 px x 1 oc-pair over ONE input channel.
// ---------------------------------------------------------------------------
__global__ void __launch_bounds__(128) k2a_conv2(const float* __restrict__ w1g) {
    const int b = blockIdx.x;                   // 0..1599
    const int slab = b >> 2, ci = b & 3;
    __shared__ __align__(16) float pp[22*24];   // one padded ci plane (528)
    __shared__ unsigned long long wq[196];      // [op4][dy7][dx7] oc pairs

    const int tid = threadIdx.x;
    for (int i = tid; i < 196; i += 128) {
        int op = i / 49, r = i - op*49;
        wq[i] = pack2(w1g[(2*op  )*196 + ci*49 + r],
                      w1g[(2*op+1)*196 + ci*49 + r]);
    }
    for (int i = tid; i < 528; i += 128) pp[i] = 0.f;
    __syncthreads();
    const float* slabp = g_p1 + (size_t)slab * 1024 + ci*256;
    for (int i = tid; i < 256; i += 128) {
        int ph = i >> 4, pw = i & 15;
        pp[(ph+3)*24 + (pw+3)] = slabp[i];
    }
    __syncthreads();

    const int ocp = tid >> 5;                // 0..3: oc pair (2ocp, 2ocp+1)
    const int l = tid & 31;
    const int h = l >> 1, ws = (l & 1) << 3; // 8-pixel segment
    unsigned long long acc[8];
#pragma unroll
    for (int px = 0; px < 8; px++) acc[px] = 0ull;

#pragma unroll
    for (int dy = 0; dy < 7; dy++) {
        const float* row = pp + (h+dy)*24 + ws;        // 16B-aligned
        float v[16];
#pragma unroll
        for (int q = 0; q < 4; q++) {
            float4 t4 = ((const float4*)row)[q];
            v[4*q+0] = t4.x; v[4*q+1] = t4.y;
            v[4*q+2] = t4.z; v[4*q+3] = t4.w;
        }
        unsigned long long pd[14];
#pragma unroll
        for (int j = 0; j < 14; j++) pd[j] = pack2(v[j], v[j]);
        const unsigned long long* wr = wq + ocp*49 + dy*7;
        unsigned long long wv[7];
#pragma unroll
        for (int dx = 0; dx < 7; dx++) wv[dx] = wr[dx];
#pragma unroll
        for (int dx = 0; dx < 7; dx++) {
#pragma unroll
            for (int px = 0; px < 8; px++)
                acc[px] = fma2(pd[px+dx], wv[dx], acc[px]);
        }
    }
    float* out = g_u2p + (size_t)ci*(NB*TT*2048)
               + (size_t)slab*2048 + (2*ocp)*256 + h*16 + ws;
    float lo[8], hi[8];
#pragma unroll
    for (int px = 0; px < 8; px++) unpack2(acc[px], lo[px], hi[px]);
    float4* d0 = (float4*)out;             // oc 2*ocp
    float4* d1 = (float4*)(out + 256);     // oc 2*ocp+1
    d0[0] = make_float4(lo[0], lo[1], lo[2], lo[3]);
    d0[1] = make_float4(lo[4], lo[5], lo[6], lo[7]);
    d1[0] = make_float4(hi[0], hi[1], hi[2], hi[3]);
    d1[1] = make_float4(hi[4], hi[5], hi[6], hi[7]);
}

// ---------------------------------------------------------------------------
// K2b: sum 4 ci partials as (c0+c1)+(c2+c3) + spike scan -> s2 bytes.
// Double-banked prefetch of 4t x 4 streams.
// ---------------------------------------------------------------------------
__global__ void __launch_bounds__(32) k2b_scan2() {
    const int g = blockIdx.x*32 + threadIdx.x;      // 0..8191
    const int n = g >> 11, r = g & 2047;
    const size_t base = (size_t)(n*TT)*2048 + r;
    const size_t PL = (size_t)(NB*TT*2048);
    const float* p0 = g_u2p + base;
    const float* p1 = g_u2p + PL   + base;
    const float* p2 = g_u2p + 2*PL + base;
    const float* p3 = g_u2p + 3*PL + base;
    unsigned char* sp = g_s2 + base;

    float A0[4], A1[4], A2[4], A3[4];
    float B0[4], B1[4], B2[4], B3[4];
#pragma unroll
    for (int i = 0; i < 4; i++) {
        A0[i] = p0[(size_t)i*2048];     A1[i] = p1[(size_t)i*2048];
        A2[i] = p2[(size_t)i*2048];     A3[i] = p3[(size_t)i*2048];
        B0[i] = p0[(size_t)(4+i)*2048]; B1[i] = p1[(size_t)(4+i)*2048];
        B2[i] = p2[(size_t)(4+i)*2048]; B3[i] = p3[(size_t)(4+i)*2048];
    }
    float m = 0.f;

#define K2B_GROUP(Q0, Q1, Q2, Q3, T0)                                        \
    {                                                                        \
        _Pragma("unroll")                                                    \
        for (int i = 0; i < 4; i++) {                                        \
            float u = (Q0[i] + Q1[i]) + (Q2[i] + Q3[i]);                     \
            m += u;                                                          \
            float s = fset_ge1(m);                                           \
            m -= s;                                                          \
            sp[(size_t)((T0) + i)*2048] = (unsigned char)s;                  \
        }                                                                    \
    }

#pragma unroll 1
    for (int tp = 0; tp < 12; tp++) {
        K2B_GROUP(A0, A1, A2, A3, tp*8);
#pragma unroll
        for (int i = 0; i < 4; i++) {
            A0[i] = p0[(size_t)(tp*8 + 8 + i)*2048];
            A1[i] = p1[(size_t)(tp*8 + 8 + i)*2048];
            A2[i] = p2[(size_t)(tp*8 + 8 + i)*2048];
            A3[i] = p3[(size_t)(tp*8 + 8 + i)*2048];
        }
        K2B_GROUP(B0, B1, B2, B3, tp*8 + 4);
        if (tp < 11) {
#pragma unroll
            for (int i = 0; i < 4; i++) {
                B0[i] = p0[(size_t)(tp*8 + 12 + i)*2048];
                B1[i] = p1[(size_t)(tp*8 + 12 + i)*2048];
                B2[i] = p2[(size_t)(tp*8 + 12 + i)*2048];
                B3[i] = p3[(size_t)(tp*8 + 12 + i)*2048];
            }
        }
    }
    K2B_GROUP(A0, A1, A2, A3, 96);
#undef K2B_GROUP
}

// ---------------------------------------------------------------------------
// K3: dp4a pool of s2 + einsum with wl -> out (n,2,t). 400 blocks x 64 thr.
// ---------------------------------------------------------------------------
__global__ void __launch_bounds__(64) k3_out(const float* __restrict__ wlg,
                                             float* __restrict__ out) {
    const int b = blockIdx.x;
    const int n = b / 100, t = b - n*100;
    const unsigned int* slab = (const unsigned int*)(g_s2 + (size_t)b * 2048);
    const int tid = threadIdx.x;
    float a0 = 0.f, a1 = 0.f;
    for (int i = tid; i < 512; i += 64) {
        int cnt = dp4a_sum(slab[i], 0);
        int cc = i >> 6;
        int hh = (i >> 2) & 15;
        int wq = i & 3;
        int wi = cc*16 + (hh >> 2)*4 + wq;
        float f = (float)cnt;
        a0 += f * wlg[wi];
        a1 += f * wlg[128 + wi];
    }
    __shared__ float r0[64], r1[64];
    r0[tid] = a0; r1[tid] = a1;
    __syncthreads();
    if (tid < 32) {
        float v0 = r0[tid] + r0[tid+32];
        float v1 = r1[tid] + r1[tid+32];
#pragma unroll
        for (int off = 16; off > 0; off >>= 1) {
            v0 += __shfl_down_sync(0xffffffffu, v0, off);
            v1 += __shfl_down_sync(0xffffffffu, v1, off);
        }
        if (tid == 0) {
            out[(n*2 + 0)*100 + t] = v0 * 0.0625f;
            out[(n*2 + 1)*100 + t] = v1 * 0.0625f;
        }
    }
}

// ---------------------------------------------------------------------------
extern "C" void kernel_launch(void* const* d_in, const int* in_sizes, int n_in,
                              void* d_out, int out_size) {
    (void)in_sizes; (void)n_in; (void)out_size;
    const float* data = (const float*)d_in[0];
    const float* w0g  = (const float*)d_in[1];
    const float* w1g  = (const float*)d_in[2];
    const float* wlg  = (const float*)d_in[3];

    // Capture-slot shift: one dummy puts k1b_scan1 in the ncu capture
    // slot (4th launch) this round.
    k_dummy  <<<   1,  32>>>();

    k0_pool  <<< 512, 512>>>(data);
    k1a_conv1<<< 400, 256>>>(w0g);
    k1b_scan1<<< 256,  64>>>();
    k2a_conv2<<<1600, 128>>>(w1g);
    k2b_scan2<<< 256,  32>>>();
    k3_out   <<< 400,  64>>>(wlg, (float*)d_out);
}